// round 5
// baseline (speedup 1.0000x reference)
#include <cuda_runtime.h>
#include <cuda_bf16.h>
#include <math.h>
#include <stdint.h>

// ---------------------------------------------------------------------------
// EGNN edge message via warp-level HMMA (mma.sync bf16, hi/lo split x3).
//   Kernel 1: P[n] = [ hh[n]@W1a + b1 | hh[n]@W1b ],  g_Xp[n] = padded x
//   Kernel 1b: pack W2/W3 mma fragments (hi/lo) into gmem tables (L1-cached)
//   Kernel 2 (per 128-edge block, 4 warps x 32 rows):
//     h1 = silu(Pa[s]+Pb[d]+r*W1row0)  (coalesced cooperative gather)
//     h2 = silu(h1@W2+b2)  mma.sync, A via ldmatrix     (edge_feature)
//          -> staged to swizzled smem, coalesced STG.128 writeback
//     h3 = silu(h2@W3+b3)  mma.sync, A built IN REGISTERS from h2 fragments
//     sc = tanh(h3.W4); trans = cd*sc/(sqrt(r)+eps)
// Output: [ radial (E) | trans (3E) | edge_feature (64E) ]
// ---------------------------------------------------------------------------

#define N_MAX_NODES 50048
__device__ float  g_P[(size_t)N_MAX_NODES * 128];
__device__ float4 g_Xp[N_MAX_NODES];
__device__ uint4  g_WF2[1024];
__device__ uint4  g_WF3[1024];

__device__ __forceinline__ float siluf(float v) {
    return __fdividef(v, 1.0f + __expf(-v));
}

// ---------------- Kernel 1: per-node projection precompute -----------------
__global__ void __launch_bounds__(256) precompute_P_kernel(
    const float* __restrict__ x,
    const float* __restrict__ hh, const float* __restrict__ W1,
    const float* __restrict__ b1, int n_nodes, int nodes_per_block)
{
    __shared__ float W1s[129 * 64];
    __shared__ float b1s[64];
    int tid = threadIdx.x;
    for (int i = tid; i < 129 * 64; i += 256) W1s[i] = W1[i];
    if (tid < 64) b1s[tid] = b1[tid];
    __syncthreads();

    int lane = tid & 31, warp = tid >> 5;
    for (int nn = warp; nn < nodes_per_block; nn += 8) {
        int n = blockIdx.x * nodes_per_block + nn;
        if (n >= n_nodes) return;
        if (lane == 0)
            g_Xp[n] = make_float4(x[3 * n], x[3 * n + 1], x[3 * n + 2], 0.f);
        float hlo = hh[(size_t)n * 64 + lane];
        float hhi = hh[(size_t)n * 64 + 32 + lane];
        float a0 = b1s[lane], a1 = b1s[lane + 32];
        float c0 = 0.f, c1 = 0.f;
        #pragma unroll
        for (int k = 0; k < 64; k++) {
            float hk = __shfl_sync(0xffffffffu, (k < 32) ? hlo : hhi, k & 31);
            a0 = fmaf(hk, W1s[(1 + k) * 64 + lane],        a0);
            a1 = fmaf(hk, W1s[(1 + k) * 64 + 32 + lane],   a1);
            c0 = fmaf(hk, W1s[(65 + k) * 64 + lane],       c0);
            c1 = fmaf(hk, W1s[(65 + k) * 64 + 32 + lane],  c1);
        }
        float* Pr = g_P + (size_t)n * 128;
        Pr[lane] = a0; Pr[lane + 32] = a1;
        Pr[64 + lane] = c0; Pr[96 + lane] = c1;
    }
}

// ------------------------------ helpers ------------------------------------
__device__ __forceinline__ void split_pair(float a, float b,
                                           uint32_t& hi, uint32_t& lo) {
    __nv_bfloat162 h2 = __floats2bfloat162_rn(a, b);
    float ra = a - __bfloat162float(h2.x);
    float rb = b - __bfloat162float(h2.y);
    __nv_bfloat162 l2 = __floats2bfloat162_rn(ra, rb);
    hi = *reinterpret_cast<uint32_t*>(&h2);
    lo = *reinterpret_cast<uint32_t*>(&l2);
}

// ---------------- Kernel 1b: pack W2/W3 mma fragment tables -----------------
__global__ void __launch_bounds__(128) pack_wf_kernel(
    const float* __restrict__ W2, const float* __restrict__ W3)
{
    int idx = blockIdx.x * 128 + threadIdx.x;
    if (idx >= 1024) return;
    int t = idx >> 5, l = idx & 31;
    int kt = t & 3, nt = t >> 2;
    int g = l >> 2, tg = l & 3;
    int k0 = kt * 16 + tg * 2;
    int n = nt * 8 + g;
    #pragma unroll
    for (int layer = 0; layer < 2; layer++) {
        const float* W = layer ? W3 : W2;
        float w00 = W[k0 * 64 + n],       w01 = W[(k0 + 1) * 64 + n];
        float w10 = W[(k0 + 8) * 64 + n], w11 = W[(k0 + 9) * 64 + n];
        uint4 v;
        split_pair(w00, w01, v.x, v.z);
        split_pair(w10, w11, v.y, v.w);
        (layer ? g_WF3 : g_WF2)[idx] = v;
    }
}

#define STS64(addr, v0, v1) \
    asm volatile("st.shared.v2.b32 [%0], {%1,%2};" \
                 :: "r"(addr), "r"(v0), "r"(v1) : "memory")

__device__ __forceinline__ void ldmx4(uint32_t* r, uint32_t addr) {
    asm volatile("ldmatrix.sync.aligned.m8n8.x4.shared.b16 {%0,%1,%2,%3}, [%4];"
        : "=r"(r[0]), "=r"(r[1]), "=r"(r[2]), "=r"(r[3]) : "r"(addr));
}

__device__ __forceinline__ void mma16816(float* d, const uint32_t* a,
                                         const uint32_t* b) {
    asm volatile(
        "mma.sync.aligned.m16n8k16.row.col.f32.bf16.bf16.f32 "
        "{%0,%1,%2,%3}, {%4,%5,%6,%7}, {%8,%9}, {%0,%1,%2,%3};"
        : "+f"(d[0]), "+f"(d[1]), "+f"(d[2]), "+f"(d[3])
        : "r"(a[0]), "r"(a[1]), "r"(a[2]), "r"(a[3]), "r"(b[0]), "r"(b[1]));
}

// smem: A tile (hi 0..16K, lo 16K..32K); fp32 stage OVERLAYS [0,32K) after
// ldmatrix has consumed the A tile. Vectors at 32K.
#define OFF_AHI  0
#define OFF_ALO  16384
#define OFF_VEC  32768
#define SMEM_TOTAL 33792

// stage swizzle: 16B chunk ch (0..15) of row r lives at word
//   r*64 + ((ch ^ SWZ(r)) << 2)
#define SWZ(r) ((((r) & 7) << 1) | (((r) >> 2) & 1))

// ---------------------------- Kernel 2: edges -------------------------------
__global__ void __launch_bounds__(128, 5) edge_mma_kernel(
    const int* __restrict__ src, const int* __restrict__ dst,
    const float* __restrict__ W1,
    const float* __restrict__ b2, const float* __restrict__ b3,
    const float* __restrict__ W4,
    float* __restrict__ out, int E)
{
    extern __shared__ char sm[];
    uint32_t smb = (uint32_t)__cvta_generic_to_shared(sm);
    float* stg = (float*)sm;
    int tid = threadIdx.x;
    int lane = tid & 31;
    int warp = tid >> 5;
    int m0 = warp * 32;
    int gid = lane >> 2, tig = lane & 3;

    float* w1r = (float*)(sm + OFF_VEC);
    float* b2v = (float*)(sm + OFF_VEC + 256);
    float* b3v = (float*)(sm + OFF_VEC + 512);
    float* w4v = (float*)(sm + OFF_VEC + 768);
    if (tid < 64) {
        w1r[tid] = W1[tid];
        b2v[tid] = b2[tid];
        b3v[tid] = b3[tid];
        w4v[tid] = W4[tid];
    }
    __syncthreads();

    // ---- edge prep: one edge per thread = row (m0+lane) of the tile ----
    int base = blockIdx.x * 128;
    int e = base + m0 + lane;
    bool valid = e < E;
    int s = 0, dn = 0;
    if (valid) { s = src[e]; dn = dst[e]; }
    float4 xs = g_Xp[s], xd = g_Xp[dn];
    float cx = xs.x - xd.x, cy = xs.y - xd.y, cz = xs.z - xd.z;
    float r = cx * cx + cy * cy + cz * cz;
    if (valid) out[e] = r;

    uint32_t aHi = smb + OFF_AHI, aLo = smb + OFF_ALO;

    // ---- layer 1: cooperative coalesced gather + silu -> smem A tile ----
    {
        const float4* w1q = (const float4*)w1r;
        int g = lane >> 3, c = lane & 7;
        const char* Pb = (const char*)g_P;
        #pragma unroll
        for (int j = 0; j < 8; j++) {
            int sl = j * 4 + g;
            int sE = __shfl_sync(0xffffffffu, s,  sl);
            int dE = __shfl_sync(0xffffffffu, dn, sl);
            float rE = __shfl_sync(0xffffffffu, r, sl);
            int row = m0 + j * 4 + g;
            uint32_t rowHi = aHi + (uint32_t)row * 128;
            uint32_t rowLo = aLo + (uint32_t)row * 128;
            int rx = row & 7;
            #pragma unroll
            for (int half = 0; half < 2; half++) {
                int q = half * 8 + c;
                float4 a = *(const float4*)(Pb + (size_t)sE * 512 + half * 128 + c * 16);
                float4 b = *(const float4*)(Pb + (size_t)dE * 512 + 256 + half * 128 + c * 16);
                float4 w = w1q[q];
                float h0 = siluf(fmaf(rE, w.x, a.x + b.x));
                float h1 = siluf(fmaf(rE, w.y, a.y + b.y));
                float h2 = siluf(fmaf(rE, w.z, a.z + b.z));
                float h3 = siluf(fmaf(rE, w.w, a.w + b.w));
                uint32_t hi0, lo0, hi1, lo1;
                split_pair(h0, h1, hi0, lo0);
                split_pair(h2, h3, hi1, lo1);
                uint32_t off = (uint32_t)((((q >> 1) ^ rx) << 4) + (q & 1) * 8);
                STS64(rowHi + off, hi0, hi1);
                STS64(rowLo + off, lo0, lo1);
            }
        }
    }
    __syncwarp();

    // ---- layer 2 GEMM: A via ldmatrix, W frags from gmem (L1-cached) ----
    float D[2][8][4];
    {
        uint32_t AH[2][4][4], AL[2][4][4];
        int Lmat = lane >> 3;
        #pragma unroll
        for (int mt = 0; mt < 2; mt++) {
            #pragma unroll
            for (int kt = 0; kt < 4; kt++) {
                int rr = m0 + mt * 16 + (Lmat & 1) * 8 + (lane & 7);
                int chunk = kt * 2 + (Lmat >> 1);
                uint32_t off = (uint32_t)(rr * 128 + ((chunk ^ (rr & 7)) << 4));
                ldmx4(AH[mt][kt], aHi + off);
                ldmx4(AL[mt][kt], aLo + off);
            }
        }
        #pragma unroll
        for (int mt = 0; mt < 2; mt++)
            #pragma unroll
            for (int nt = 0; nt < 8; nt++) {
                float b0 = b2v[nt * 8 + tig * 2];
                float b1 = b2v[nt * 8 + tig * 2 + 1];
                D[mt][nt][0] = b0; D[mt][nt][1] = b1;
                D[mt][nt][2] = b0; D[mt][nt][3] = b1;
            }
        #pragma unroll
        for (int nt = 0; nt < 8; nt++) {
            uint4 w[4];
            #pragma unroll
            for (int kt = 0; kt < 4; kt++)
                w[kt] = __ldg(&g_WF2[(nt * 4 + kt) * 32 + lane]);
            #pragma unroll
            for (int kt = 0; kt < 4; kt++) {
                uint32_t bh[2] = { w[kt].x, w[kt].y };
                uint32_t bl[2] = { w[kt].z, w[kt].w };
                #pragma unroll
                for (int mt = 0; mt < 2; mt++) {
                    mma16816(D[mt][nt], AH[mt][kt], bh);
                    mma16816(D[mt][nt], AH[mt][kt], bl);
                    mma16816(D[mt][nt], AL[mt][kt], bh);
                }
            }
        }
    }

    // A tile fully consumed by all warps before staging overlays it.
    __syncthreads();

    // ---- layer 2 epilogue: h2 = silu(D+b2) -> swizzled fp32 stage + A3 regs
    uint32_t A3H[2][4][4], A3L[2][4][4];
    {
        #pragma unroll
        for (int mt = 0; mt < 2; mt++) {
            int r0 = m0 + mt * 16 + gid;
            int r1 = r0 + 8;
            #pragma unroll
            for (int nt = 0; nt < 8; nt++) {
                float v0 = siluf(D[mt][nt][0]);
                float v1 = siluf(D[mt][nt][1]);
                float v2 = siluf(D[mt][nt][2]);
                float v3 = siluf(D[mt][nt][3]);
                int ch = 2 * nt + (tig >> 1);
                int w0 = r0 * 64 + ((ch ^ SWZ(r0)) << 2) + (tig & 1) * 2;
                int w1 = r1 * 64 + ((ch ^ SWZ(r1)) << 2) + (tig & 1) * 2;
                *(float2*)(stg + w0) = make_float2(v0, v1);
                *(float2*)(stg + w1) = make_float2(v2, v3);
                // D fragment layout == A fragment layout for next GEMM:
                int kt = nt >> 1, hi = (nt & 1) * 2;
                split_pair(v0, v1, A3H[mt][kt][hi],     A3L[mt][kt][hi]);
                split_pair(v2, v3, A3H[mt][kt][hi + 1], A3L[mt][kt][hi + 1]);
            }
        }
    }
    __syncthreads();

    // ---- layer 3 GEMM: A from registers, W frags from gmem ----
    {
        #pragma unroll
        for (int mt = 0; mt < 2; mt++)
            #pragma unroll
            for (int nt = 0; nt < 8; nt++) {
                float b0 = b3v[nt * 8 + tig * 2];
                float b1 = b3v[nt * 8 + tig * 2 + 1];
                D[mt][nt][0] = b0; D[mt][nt][1] = b1;
                D[mt][nt][2] = b0; D[mt][nt][3] = b1;
            }
        #pragma unroll
        for (int nt = 0; nt < 8; nt++) {
            uint4 w[4];
            #pragma unroll
            for (int kt = 0; kt < 4; kt++)
                w[kt] = __ldg(&g_WF3[(nt * 4 + kt) * 32 + lane]);
            #pragma unroll
            for (int kt = 0; kt < 4; kt++) {
                uint32_t bh[2] = { w[kt].x, w[kt].y };
                uint32_t bl[2] = { w[kt].z, w[kt].w };
                #pragma unroll
                for (int mt = 0; mt < 2; mt++) {
                    mma16816(D[mt][nt], A3H[mt][kt], bh);
                    mma16816(D[mt][nt], A3H[mt][kt], bl);
                    mma16816(D[mt][nt], A3L[mt][kt], bh);
                }
            }
        }
    }

    // ---- layer 3 epilogue: sc = tanh(silu(D+b3).W4); trans ----
    {
        float dv[2][2] = { {0.f, 0.f}, {0.f, 0.f} };
        #pragma unroll
        for (int mt = 0; mt < 2; mt++) {
            #pragma unroll
            for (int nt = 0; nt < 8; nt++) {
                int col = nt * 8 + tig * 2;
                float wa = w4v[col], wb = w4v[col + 1];
                dv[mt][0] = fmaf(siluf(D[mt][nt][0]), wa,
                            fmaf(siluf(D[mt][nt][1]), wb, dv[mt][0]));
                dv[mt][1] = fmaf(siluf(D[mt][nt][2]), wa,
                            fmaf(siluf(D[mt][nt][3]), wb, dv[mt][1]));
            }
        }
        #pragma unroll
        for (int mt = 0; mt < 2; mt++) {
            #pragma unroll
            for (int half = 0; half < 2; half++) {
                dv[mt][half] += __shfl_xor_sync(0xffffffffu, dv[mt][half], 1);
                dv[mt][half] += __shfl_xor_sync(0xffffffffu, dv[mt][half], 2);
            }
        }
        float dsel = (tig == 0) ? dv[0][0] : (tig == 1) ? dv[0][1]
                   : (tig == 2) ? dv[1][0] : dv[1][1];
        int rw = (tig >> 1) * 16 + (tig & 1) * 8 + gid;
        float rr  = __shfl_sync(0xffffffffu, r,  rw);
        float cxx = __shfl_sync(0xffffffffu, cx, rw);
        float cyy = __shfl_sync(0xffffffffu, cy, rw);
        float czz = __shfl_sync(0xffffffffu, cz, rw);
        int ee = base + m0 + rw;
        float msc = __fdividef(tanhf(dsel), sqrtf(rr) + 1e-8f);
        if (ee < E) {
            float* outT = out + E;
            outT[3 * ee + 0] = cxx * msc;
            outT[3 * ee + 1] = cyy * msc;
            outT[3 * ee + 2] = czz * msc;
        }
    }

    // ---- coalesced feature writeback from stage ----
    {
        float* fout = out + (size_t)4 * E;
        #pragma unroll
        for (int it = 0; it < 16; it++) {
            int idx = it * 128 + tid;
            int rr = idx >> 4, q = idx & 15;
            if (base + rr < E) {
                int w = rr * 64 + ((q ^ SWZ(rr)) << 2);
                float4 v = *(const float4*)(stg + w);
                *(float4*)(fout + (size_t)(base + rr) * 64 + q * 4) = v;
            }
        }
    }
}

extern "C" void kernel_launch(void* const* d_in, const int* in_sizes, int n_in,
                              void* d_out, int out_size) {
    const float* x  = (const float*)d_in[0];
    const float* hh = (const float*)d_in[1];
    const int* src  = (const int*)d_in[2];
    const int* dst  = (const int*)d_in[3];
    const float* W1 = (const float*)d_in[4];
    const float* b1 = (const float*)d_in[5];
    const float* W2 = (const float*)d_in[6];
    const float* b2 = (const float*)d_in[7];
    const float* W3 = (const float*)d_in[8];
    const float* b3 = (const float*)d_in[9];
    const float* W4 = (const float*)d_in[10];
    int N = in_sizes[0] / 3;
    int E = in_sizes[2];
    float* out = (float*)d_out;

    cudaFuncSetAttribute(edge_mma_kernel,
                         cudaFuncAttributeMaxDynamicSharedMemorySize, SMEM_TOTAL);
    cudaFuncSetAttribute(edge_mma_kernel,
                         cudaFuncAttributePreferredSharedMemoryCarveout, 75);

    const int npb = 80;
    int pblocks = (N + npb - 1) / npb;
    precompute_P_kernel<<<pblocks, 256>>>(x, hh, W1, b1, N, npb);
    pack_wf_kernel<<<8, 128>>>(W2, W3);

    int eblocks = (E + 127) / 128;
    edge_mma_kernel<<<eblocks, 128, SMEM_TOTAL>>>(src, dst, W1, b2, b3,
                                                  W4, out, E);
    (void)n_in; (void)out_size;
}

// round 6
// speedup vs baseline: 2.1653x; 2.1653x over previous
#include <cuda_runtime.h>
#include <cuda_bf16.h>
#include <math.h>
#include <stdint.h>

// ---------------------------------------------------------------------------
// EGNN edge message via warp-level HMMA (mma.sync bf16, hi/lo split x3).
//   Kernel 1: P[n] = [ hh[n]@W1a + b1 | hh[n]@W1b ],  g_Xp[n] = padded x
//   Kernel 1b: pack W2/W3 mma fragments (hi/lo) into gmem tables (L1-cached)
//   Kernel 2 (per 128-edge block, 4 warps x 32 rows, mt-sequential to keep
//   registers ~110 -> 4 blocks/SM without spills):
//     h1 = silu(Pa[s]+Pb[d]+r*W1row0)  (coalesced cooperative gather)
//     per 16-row half: h2 = silu(h1@W2+b2) (features out, A3 regs built)
//                      h3 = silu(h2@W3+b3); sc = tanh(h3.W4); trans
// Output: [ radial (E) | trans (3E) | edge_feature (64E) ]
// ---------------------------------------------------------------------------

#define N_MAX_NODES 50048
__device__ float  g_P[(size_t)N_MAX_NODES * 128];
__device__ float4 g_Xp[N_MAX_NODES];
__device__ uint4  g_WF2[1024];
__device__ uint4  g_WF3[1024];

__device__ __forceinline__ float siluf(float v) {
    return __fdividef(v, 1.0f + __expf(-v));
}

// ---------------- Kernel 1: per-node projection precompute -----------------
__global__ void __launch_bounds__(256) precompute_P_kernel(
    const float* __restrict__ x,
    const float* __restrict__ hh, const float* __restrict__ W1,
    const float* __restrict__ b1, int n_nodes, int nodes_per_block)
{
    __shared__ float W1s[129 * 64];
    __shared__ float b1s[64];
    int tid = threadIdx.x;
    for (int i = tid; i < 129 * 64; i += 256) W1s[i] = W1[i];
    if (tid < 64) b1s[tid] = b1[tid];
    __syncthreads();

    int lane = tid & 31, warp = tid >> 5;
    for (int nn = warp; nn < nodes_per_block; nn += 8) {
        int n = blockIdx.x * nodes_per_block + nn;
        if (n >= n_nodes) return;
        if (lane == 0)
            g_Xp[n] = make_float4(x[3 * n], x[3 * n + 1], x[3 * n + 2], 0.f);
        float hlo = hh[(size_t)n * 64 + lane];
        float hhi = hh[(size_t)n * 64 + 32 + lane];
        float a0 = b1s[lane], a1 = b1s[lane + 32];
        float c0 = 0.f, c1 = 0.f;
        #pragma unroll
        for (int k = 0; k < 64; k++) {
            float hk = __shfl_sync(0xffffffffu, (k < 32) ? hlo : hhi, k & 31);
            a0 = fmaf(hk, W1s[(1 + k) * 64 + lane],        a0);
            a1 = fmaf(hk, W1s[(1 + k) * 64 + 32 + lane],   a1);
            c0 = fmaf(hk, W1s[(65 + k) * 64 + lane],       c0);
            c1 = fmaf(hk, W1s[(65 + k) * 64 + 32 + lane],  c1);
        }
        float* Pr = g_P + (size_t)n * 128;
        Pr[lane] = a0; Pr[lane + 32] = a1;
        Pr[64 + lane] = c0; Pr[96 + lane] = c1;
    }
}

// ------------------------------ helpers ------------------------------------
__device__ __forceinline__ void split_pair(float a, float b,
                                           uint32_t& hi, uint32_t& lo) {
    __nv_bfloat162 h2 = __floats2bfloat162_rn(a, b);
    float ra = a - __bfloat162float(h2.x);
    float rb = b - __bfloat162float(h2.y);
    __nv_bfloat162 l2 = __floats2bfloat162_rn(ra, rb);
    hi = *reinterpret_cast<uint32_t*>(&h2);
    lo = *reinterpret_cast<uint32_t*>(&l2);
}

// ---------------- Kernel 1b: pack W2/W3 mma fragment tables -----------------
__global__ void __launch_bounds__(128) pack_wf_kernel(
    const float* __restrict__ W2, const float* __restrict__ W3)
{
    int idx = blockIdx.x * 128 + threadIdx.x;
    if (idx >= 1024) return;
    int t = idx >> 5, l = idx & 31;
    int kt = t & 3, nt = t >> 2;
    int g = l >> 2, tg = l & 3;
    int k0 = kt * 16 + tg * 2;
    int n = nt * 8 + g;
    #pragma unroll
    for (int layer = 0; layer < 2; layer++) {
        const float* W = layer ? W3 : W2;
        float w00 = W[k0 * 64 + n],       w01 = W[(k0 + 1) * 64 + n];
        float w10 = W[(k0 + 8) * 64 + n], w11 = W[(k0 + 9) * 64 + n];
        uint4 v;
        split_pair(w00, w01, v.x, v.z);
        split_pair(w10, w11, v.y, v.w);
        (layer ? g_WF3 : g_WF2)[idx] = v;
    }
}

#define STS64(addr, v0, v1) \
    asm volatile("st.shared.v2.b32 [%0], {%1,%2};" \
                 :: "r"(addr), "r"(v0), "r"(v1) : "memory")

__device__ __forceinline__ void ldmx4(uint32_t* r, uint32_t addr) {
    asm volatile("ldmatrix.sync.aligned.m8n8.x4.shared.b16 {%0,%1,%2,%3}, [%4];"
        : "=r"(r[0]), "=r"(r[1]), "=r"(r[2]), "=r"(r[3]) : "r"(addr));
}

__device__ __forceinline__ void mma16816(float* d, const uint32_t* a,
                                         const uint32_t* b) {
    asm volatile(
        "mma.sync.aligned.m16n8k16.row.col.f32.bf16.bf16.f32 "
        "{%0,%1,%2,%3}, {%4,%5,%6,%7}, {%8,%9}, {%0,%1,%2,%3};"
        : "+f"(d[0]), "+f"(d[1]), "+f"(d[2]), "+f"(d[3])
        : "r"(a[0]), "r"(a[1]), "r"(a[2]), "r"(a[3]), "r"(b[0]), "r"(b[1]));
}

// smem: A tile hi [0,16K), lo [16K,32K), vectors at 32K. 33.8KB -> 4 blocks/SM.
#define OFF_AHI  0
#define OFF_ALO  16384
#define OFF_VEC  32768
#define SMEM_TOTAL 33792

// ---------------------------- Kernel 2: edges -------------------------------
__global__ void __launch_bounds__(128, 4) edge_mma_kernel(
    const int* __restrict__ src, const int* __restrict__ dst,
    const float* __restrict__ W1,
    const float* __restrict__ b2, const float* __restrict__ b3,
    const float* __restrict__ W4,
    float* __restrict__ out, int E)
{
    extern __shared__ char sm[];
    uint32_t smb = (uint32_t)__cvta_generic_to_shared(sm);
    int tid = threadIdx.x;
    int lane = tid & 31;
    int warp = tid >> 5;
    int m0 = warp * 32;
    int gid = lane >> 2, tig = lane & 3;

    float* w1r = (float*)(sm + OFF_VEC);
    float* b2v = (float*)(sm + OFF_VEC + 256);
    float* b3v = (float*)(sm + OFF_VEC + 512);
    float* w4v = (float*)(sm + OFF_VEC + 768);
    if (tid < 64) {
        w1r[tid] = W1[tid];
        b2v[tid] = b2[tid];
        b3v[tid] = b3[tid];
        w4v[tid] = W4[tid];
    }
    __syncthreads();

    // ---- edge prep: one edge per thread = row (m0+lane) of the tile ----
    int base = blockIdx.x * 128;
    int e = base + m0 + lane;
    bool valid = e < E;
    int s = 0, dn = 0;
    if (valid) { s = src[e]; dn = dst[e]; }
    float4 xs = g_Xp[s], xd = g_Xp[dn];
    float cx = xs.x - xd.x, cy = xs.y - xd.y, cz = xs.z - xd.z;
    float r = cx * cx + cy * cy + cz * cz;
    if (valid) out[e] = r;

    uint32_t aHi = smb + OFF_AHI, aLo = smb + OFF_ALO;

    // ---- layer 1: cooperative coalesced gather + silu -> smem A tile ----
    {
        const float4* w1q = (const float4*)w1r;
        int g = lane >> 3, c = lane & 7;
        const char* Pb = (const char*)g_P;
        #pragma unroll
        for (int j = 0; j < 8; j++) {
            int sl = j * 4 + g;
            int sE = __shfl_sync(0xffffffffu, s,  sl);
            int dE = __shfl_sync(0xffffffffu, dn, sl);
            float rE = __shfl_sync(0xffffffffu, r, sl);
            int row = m0 + j * 4 + g;
            uint32_t rowHi = aHi + (uint32_t)row * 128;
            uint32_t rowLo = aLo + (uint32_t)row * 128;
            int rx = row & 7;
            #pragma unroll
            for (int half = 0; half < 2; half++) {
                int q = half * 8 + c;
                float4 a = *(const float4*)(Pb + (size_t)sE * 512 + half * 128 + c * 16);
                float4 b = *(const float4*)(Pb + (size_t)dE * 512 + 256 + half * 128 + c * 16);
                float4 w = w1q[q];
                float h0 = siluf(fmaf(rE, w.x, a.x + b.x));
                float h1 = siluf(fmaf(rE, w.y, a.y + b.y));
                float h2 = siluf(fmaf(rE, w.z, a.z + b.z));
                float h3 = siluf(fmaf(rE, w.w, a.w + b.w));
                uint32_t hi0, lo0, hi1, lo1;
                split_pair(h0, h1, hi0, lo0);
                split_pair(h2, h3, hi1, lo1);
                uint32_t off = (uint32_t)((((q >> 1) ^ rx) << 4) + (q & 1) * 8);
                STS64(rowHi + off, hi0, hi1);
                STS64(rowLo + off, lo0, lo1);
            }
        }
    }
    __syncwarp();

    // ---- two sequential 16-row pipelines (registers stay ~110) ----
    float* fout = out + (size_t)4 * E;
    float* outT = out + E;
    int Lmat = lane >> 3;

    #pragma unroll 1
    for (int mt = 0; mt < 2; mt++) {
        // -- layer 2 GEMM: A via ldmatrix, W frags from gmem (L1-cached) --
        float D[8][4];
        uint32_t A3H[4][4], A3L[4][4];
        {
            uint32_t AH[4][4], AL[4][4];
            #pragma unroll
            for (int kt = 0; kt < 4; kt++) {
                int rr = m0 + mt * 16 + (Lmat & 1) * 8 + (lane & 7);
                int chunk = kt * 2 + (Lmat >> 1);
                uint32_t off = (uint32_t)(rr * 128 + ((chunk ^ (rr & 7)) << 4));
                ldmx4(AH[kt], aHi + off);
                ldmx4(AL[kt], aLo + off);
            }
            #pragma unroll
            for (int nt = 0; nt < 8; nt++) {
                float b0 = b2v[nt * 8 + tig * 2];
                float b1 = b2v[nt * 8 + tig * 2 + 1];
                D[nt][0] = b0; D[nt][1] = b1;
                D[nt][2] = b0; D[nt][3] = b1;
            }
            #pragma unroll
            for (int nt = 0; nt < 8; nt++) {
                #pragma unroll
                for (int kt = 0; kt < 4; kt++) {
                    uint4 w = __ldg(&g_WF2[(nt * 4 + kt) * 32 + lane]);
                    uint32_t bh[2] = { w.x, w.y };
                    uint32_t bl[2] = { w.z, w.w };
                    mma16816(D[nt], AH[kt], bh);
                    mma16816(D[nt], AH[kt], bl);
                    mma16816(D[nt], AL[kt], bh);
                }
            }
        }

        // -- layer 2 epilogue: features out + A3 fragments in registers --
        {
            int r0 = m0 + mt * 16 + gid;
            int r1 = r0 + 8;
            int e0 = base + r0, e1 = base + r1;
            #pragma unroll
            for (int nt = 0; nt < 8; nt++) {
                float v0 = siluf(D[nt][0]);
                float v1 = siluf(D[nt][1]);
                float v2 = siluf(D[nt][2]);
                float v3 = siluf(D[nt][3]);
                int col = nt * 8 + tig * 2;
                if (e0 < E)
                    *(float2*)(fout + (size_t)e0 * 64 + col) = make_float2(v0, v1);
                if (e1 < E)
                    *(float2*)(fout + (size_t)e1 * 64 + col) = make_float2(v2, v3);
                int kt = nt >> 1, hi = (nt & 1) * 2;
                split_pair(v0, v1, A3H[kt][hi],     A3L[kt][hi]);
                split_pair(v2, v3, A3H[kt][hi + 1], A3L[kt][hi + 1]);
            }
        }

        // -- layer 3 GEMM: A from registers --
        #pragma unroll
        for (int nt = 0; nt < 8; nt++) {
            float b0 = b3v[nt * 8 + tig * 2];
            float b1 = b3v[nt * 8 + tig * 2 + 1];
            D[nt][0] = b0; D[nt][1] = b1;
            D[nt][2] = b0; D[nt][3] = b1;
        }
        #pragma unroll
        for (int nt = 0; nt < 8; nt++) {
            #pragma unroll
            for (int kt = 0; kt < 4; kt++) {
                uint4 w = __ldg(&g_WF3[(nt * 4 + kt) * 32 + lane]);
                uint32_t bh[2] = { w.x, w.y };
                uint32_t bl[2] = { w.z, w.w };
                mma16816(D[nt], A3H[kt], bh);
                mma16816(D[nt], A3H[kt], bl);
                mma16816(D[nt], A3L[kt], bh);
            }
        }

        // -- layer 3 epilogue: sc = tanh(silu(D+b3).W4); trans --
        {
            float dv0 = 0.f, dv1 = 0.f;
            #pragma unroll
            for (int nt = 0; nt < 8; nt++) {
                int col = nt * 8 + tig * 2;
                float wa = w4v[col], wb = w4v[col + 1];
                dv0 = fmaf(siluf(D[nt][0]), wa, fmaf(siluf(D[nt][1]), wb, dv0));
                dv1 = fmaf(siluf(D[nt][2]), wa, fmaf(siluf(D[nt][3]), wb, dv1));
            }
            dv0 += __shfl_xor_sync(0xffffffffu, dv0, 1);
            dv0 += __shfl_xor_sync(0xffffffffu, dv0, 2);
            dv1 += __shfl_xor_sync(0xffffffffu, dv1, 1);
            dv1 += __shfl_xor_sync(0xffffffffu, dv1, 2);
            // rows mt*16+gid (dv0) and mt*16+8+gid (dv1); lanes tig 0/1 store
            int rw = mt * 16 + (tig & 1) * 8 + gid;
            float dsel = (tig & 1) ? dv1 : dv0;
            float rr  = __shfl_sync(0xffffffffu, r,  rw);
            float cxx = __shfl_sync(0xffffffffu, cx, rw);
            float cyy = __shfl_sync(0xffffffffu, cy, rw);
            float czz = __shfl_sync(0xffffffffu, cz, rw);
            int ee = base + m0 + rw;
            float msc = __fdividef(tanhf(dsel), sqrtf(rr) + 1e-8f);
            if (tig < 2 && ee < E) {
                outT[3 * ee + 0] = cxx * msc;
                outT[3 * ee + 1] = cyy * msc;
                outT[3 * ee + 2] = czz * msc;
            }
        }
    }
}

extern "C" void kernel_launch(void* const* d_in, const int* in_sizes, int n_in,
                              void* d_out, int out_size) {
    const float* x  = (const float*)d_in[0];
    const float* hh = (const float*)d_in[1];
    const int* src  = (const int*)d_in[2];
    const int* dst  = (const int*)d_in[3];
    const float* W1 = (const float*)d_in[4];
    const float* b1 = (const float*)d_in[5];
    const float* W2 = (const float*)d_in[6];
    const float* b2 = (const float*)d_in[7];
    const float* W3 = (const float*)d_in[8];
    const float* b3 = (const float*)d_in[9];
    const float* W4 = (const float*)d_in[10];
    int N = in_sizes[0] / 3;
    int E = in_sizes[2];
    float* out = (float*)d_out;

    cudaFuncSetAttribute(edge_mma_kernel,
                         cudaFuncAttributeMaxDynamicSharedMemorySize, SMEM_TOTAL);

    const int npb = 80;
    int pblocks = (N + npb - 1) / npb;
    precompute_P_kernel<<<pblocks, 256>>>(x, hh, W1, b1, N, npb);
    pack_wf_kernel<<<8, 128>>>(W2, W3);

    int eblocks = (E + 127) / 128;
    edge_mma_kernel<<<eblocks, 128, SMEM_TOTAL>>>(src, dst, W1, b2, b3,
                                                  W4, out, E);
    (void)n_in; (void)out_size;
}

// round 7
// speedup vs baseline: 2.5042x; 1.1565x over previous
#include <cuda_runtime.h>
#include <cuda_bf16.h>
#include <math.h>
#include <stdint.h>

// ---------------------------------------------------------------------------
// EGNN edge message via warp-level HMMA (mma.sync bf16, hi/lo split x3).
//   Kernel 0: pack W1a/W1b/W2/W3 mma fragment tables (hi/lo) into gmem
//   Kernel 1: P[n] = [ hh[n]@W1a + b1 | hh[n]@W1b ] via HMMA; g_Xp[n] = x pad
//   Kernel 2 (per 128-edge block, 4 warps x 32 rows, mt-sequential):
//     h1 = silu(Pa[s]+Pb[d]+r*W1row0)  (coalesced cooperative gather)
//     per 16-row half: h2 = silu(h1@W2+b2) (features out, A3 regs built)
//                      h3 = silu(h2@W3+b3); sc = tanh(h3.W4); trans
// Output: [ radial (E) | trans (3E) | edge_feature (64E) ]
// ---------------------------------------------------------------------------

#define N_MAX_NODES 50048
__device__ float  g_P[(size_t)N_MAX_NODES * 128];
__device__ float4 g_Xp[N_MAX_NODES];
__device__ uint4  g_WF1A[1024];
__device__ uint4  g_WF1B[1024];
__device__ uint4  g_WF2[1024];
__device__ uint4  g_WF3[1024];

__device__ __forceinline__ float siluf(float v) {
    return __fdividef(v, 1.0f + __expf(-v));
}

__device__ __forceinline__ void split_pair(float a, float b,
                                           uint32_t& hi, uint32_t& lo) {
    __nv_bfloat162 h2 = __floats2bfloat162_rn(a, b);
    float ra = a - __bfloat162float(h2.x);
    float rb = b - __bfloat162float(h2.y);
    __nv_bfloat162 l2 = __floats2bfloat162_rn(ra, rb);
    hi = *reinterpret_cast<uint32_t*>(&h2);
    lo = *reinterpret_cast<uint32_t*>(&l2);
}

// ---------------- Kernel 0: pack mma fragment tables -----------------------
// fragment idx: t = idx>>5 (kt = t&3, nt = t>>2), lane l = idx&31
// uint4 = { hi(k0,n),(k0+1,n) , hi(k0+8,n),(k0+9,n) , lo..., lo... }
__global__ void __launch_bounds__(128) pack_wf_kernel(
    const float* __restrict__ W1,
    const float* __restrict__ W2, const float* __restrict__ W3)
{
    int idx = blockIdx.x * 128 + threadIdx.x;
    if (idx >= 1024) return;
    int t = idx >> 5, l = idx & 31;
    int kt = t & 3, nt = t >> 2;
    int g = l >> 2, tg = l & 3;
    int k0 = kt * 16 + tg * 2;
    int n = nt * 8 + g;
    #pragma unroll
    for (int tab = 0; tab < 4; tab++) {
        const float* W;
        int ld = 64, roff = 0;
        uint4* dstv;
        if (tab == 0)      { W = W1; roff = 1;  dstv = g_WF1A; }
        else if (tab == 1) { W = W1; roff = 65; dstv = g_WF1B; }
        else if (tab == 2) { W = W2; dstv = g_WF2; }
        else               { W = W3; dstv = g_WF3; }
        float w00 = W[(roff + k0) * ld + n],     w01 = W[(roff + k0 + 1) * ld + n];
        float w10 = W[(roff + k0 + 8) * ld + n], w11 = W[(roff + k0 + 9) * ld + n];
        uint4 v;
        split_pair(w00, w01, v.x, v.z);
        split_pair(w10, w11, v.y, v.w);
        dstv[idx] = v;
    }
}

// ------------------------------ mma helpers ---------------------------------
#define STS64(addr, v0, v1) \
    asm volatile("st.shared.v2.b32 [%0], {%1,%2};" \
                 :: "r"(addr), "r"(v0), "r"(v1) : "memory")

__device__ __forceinline__ void ldmx4(uint32_t* r, uint32_t addr) {
    asm volatile("ldmatrix.sync.aligned.m8n8.x4.shared.b16 {%0,%1,%2,%3}, [%4];"
        : "=r"(r[0]), "=r"(r[1]), "=r"(r[2]), "=r"(r[3]) : "r"(addr));
}

__device__ __forceinline__ void mma16816(float* d, const uint32_t* a,
                                         const uint32_t* b) {
    asm volatile(
        "mma.sync.aligned.m16n8k16.row.col.f32.bf16.bf16.f32 "
        "{%0,%1,%2,%3}, {%4,%5,%6,%7}, {%8,%9}, {%0,%1,%2,%3};"
        : "+f"(d[0]), "+f"(d[1]), "+f"(d[2]), "+f"(d[3])
        : "r"(a[0]), "r"(a[1]), "r"(a[2]), "r"(a[3]), "r"(b[0]), "r"(b[1]));
}

#define OFF_AHI  0
#define OFF_ALO  16384
#define OFF_VEC  32768
#define SMEM_TOTAL 33792

// ---------------- Kernel 1: per-node projection via HMMA --------------------
// P[128 nodes, 128] = hh_tile @ [W1a | W1b], + b1 on the A half.
__global__ void __launch_bounds__(128) precompute_mma_kernel(
    const float* __restrict__ x,
    const float* __restrict__ hh, const float* __restrict__ b1, int n_nodes)
{
    extern __shared__ char sm[];
    uint32_t smb = (uint32_t)__cvta_generic_to_shared(sm);
    int tid = threadIdx.x;
    int lane = tid & 31;
    int warp = tid >> 5;
    int m0 = warp * 32;
    int gid = lane >> 2, tig = lane & 3;

    float* b1v = (float*)(sm + OFF_VEC);
    if (tid < 64) b1v[tid] = b1[tid];

    int nb = blockIdx.x * 128;
    int node = nb + m0 + lane;
    if (node < n_nodes) {
        const float* xp = x + 3 * node;
        g_Xp[node] = make_float4(xp[0], xp[1], xp[2], 0.f);
    }

    uint32_t aHi = smb + OFF_AHI, aLo = smb + OFF_ALO;

    // ---- coalesced hh load -> bf16 hi/lo A tile (same layout as edge k.) ----
    {
        int g = lane >> 3, c = lane & 7;
        #pragma unroll
        for (int j = 0; j < 8; j++) {
            int row = m0 + j * 4 + g;
            int n = nb + row;
            uint32_t rowHi = aHi + (uint32_t)row * 128;
            uint32_t rowLo = aLo + (uint32_t)row * 128;
            int rx = row & 7;
            #pragma unroll
            for (int half = 0; half < 2; half++) {
                int q = half * 8 + c;
                float4 a = (n < n_nodes)
                    ? *(const float4*)(hh + (size_t)n * 64 + q * 4)
                    : make_float4(0.f, 0.f, 0.f, 0.f);
                uint32_t hi0, lo0, hi1, lo1;
                split_pair(a.x, a.y, hi0, lo0);
                split_pair(a.z, a.w, hi1, lo1);
                uint32_t off = (uint32_t)((((q >> 1) ^ rx) << 4) + (q & 1) * 8);
                STS64(rowHi + off, hi0, hi1);
                STS64(rowLo + off, lo0, lo1);
            }
        }
    }
    __syncthreads();   // b1v written by warps 0,1; A rows per-warp

    int Lmat = lane >> 3;
    #pragma unroll 1
    for (int mt = 0; mt < 2; mt++) {
        uint32_t AH[4][4], AL[4][4];
        #pragma unroll
        for (int kt = 0; kt < 4; kt++) {
            int rr = m0 + mt * 16 + (Lmat & 1) * 8 + (lane & 7);
            int chunk = kt * 2 + (Lmat >> 1);
            uint32_t off = (uint32_t)(rr * 128 + ((chunk ^ (rr & 7)) << 4));
            ldmx4(AH[kt], aHi + off);
            ldmx4(AL[kt], aLo + off);
        }
        int r0 = m0 + mt * 16 + gid;
        int r1 = r0 + 8;
        int n0 = nb + r0, n1 = nb + r1;

        #pragma unroll 1
        for (int half = 0; half < 2; half++) {
            const uint4* WF = half ? g_WF1B : g_WF1A;
            float D[8][4];
            #pragma unroll
            for (int nt = 0; nt < 8; nt++) {
                float b0 = half ? 0.f : b1v[nt * 8 + tig * 2];
                float b1x = half ? 0.f : b1v[nt * 8 + tig * 2 + 1];
                D[nt][0] = b0; D[nt][1] = b1x;
                D[nt][2] = b0; D[nt][3] = b1x;
            }
            #pragma unroll
            for (int nt = 0; nt < 8; nt++) {
                #pragma unroll
                for (int kt = 0; kt < 4; kt++) {
                    uint4 w = __ldg(&WF[(nt * 4 + kt) * 32 + lane]);
                    uint32_t bh[2] = { w.x, w.y };
                    uint32_t bl[2] = { w.z, w.w };
                    mma16816(D[nt], AH[kt], bh);
                    mma16816(D[nt], AH[kt], bl);
                    mma16816(D[nt], AL[kt], bh);
                }
            }
            #pragma unroll
            for (int nt = 0; nt < 8; nt++) {
                int col = half * 64 + nt * 8 + tig * 2;
                if (n0 < n_nodes)
                    *(float2*)(g_P + (size_t)n0 * 128 + col) =
                        make_float2(D[nt][0], D[nt][1]);
                if (n1 < n_nodes)
                    *(float2*)(g_P + (size_t)n1 * 128 + col) =
                        make_float2(D[nt][2], D[nt][3]);
            }
        }
    }
}

// ---------------------------- Kernel 2: edges -------------------------------
__global__ void __launch_bounds__(128, 4) edge_mma_kernel(
    const int* __restrict__ src, const int* __restrict__ dst,
    const float* __restrict__ W1,
    const float* __restrict__ b2, const float* __restrict__ b3,
    const float* __restrict__ W4,
    float* __restrict__ out, int E)
{
    extern __shared__ char sm[];
    uint32_t smb = (uint32_t)__cvta_generic_to_shared(sm);
    int tid = threadIdx.x;
    int lane = tid & 31;
    int warp = tid >> 5;
    int m0 = warp * 32;
    int gid = lane >> 2, tig = lane & 3;

    float* w1r = (float*)(sm + OFF_VEC);
    float* b2v = (float*)(sm + OFF_VEC + 256);
    float* b3v = (float*)(sm + OFF_VEC + 512);
    float* w4v = (float*)(sm + OFF_VEC + 768);
    if (tid < 64) {
        w1r[tid] = W1[tid];
        b2v[tid] = b2[tid];
        b3v[tid] = b3[tid];
        w4v[tid] = W4[tid];
    }
    __syncthreads();

    int base = blockIdx.x * 128;
    int e = base + m0 + lane;
    bool valid = e < E;
    int s = 0, dn = 0;
    if (valid) { s = src[e]; dn = dst[e]; }
    float4 xs = g_Xp[s], xd = g_Xp[dn];
    float cx = xs.x - xd.x, cy = xs.y - xd.y, cz = xs.z - xd.z;
    float r = cx * cx + cy * cy + cz * cz;
    if (valid) out[e] = r;

    uint32_t aHi = smb + OFF_AHI, aLo = smb + OFF_ALO;

    // ---- layer 1: cooperative coalesced gather + silu -> smem A tile ----
    {
        const float4* w1q = (const float4*)w1r;
        int g = lane >> 3, c = lane & 7;
        const char* Pb = (const char*)g_P;
        #pragma unroll
        for (int j = 0; j < 8; j++) {
            int sl = j * 4 + g;
            int sE = __shfl_sync(0xffffffffu, s,  sl);
            int dE = __shfl_sync(0xffffffffu, dn, sl);
            float rE = __shfl_sync(0xffffffffu, r, sl);
            int row = m0 + j * 4 + g;
            uint32_t rowHi = aHi + (uint32_t)row * 128;
            uint32_t rowLo = aLo + (uint32_t)row * 128;
            int rx = row & 7;
            #pragma unroll
            for (int half = 0; half < 2; half++) {
                int q = half * 8 + c;
                float4 a = *(const float4*)(Pb + (size_t)sE * 512 + half * 128 + c * 16);
                float4 b = *(const float4*)(Pb + (size_t)dE * 512 + 256 + half * 128 + c * 16);
                float4 w = w1q[q];
                float h0 = siluf(fmaf(rE, w.x, a.x + b.x));
                float h1 = siluf(fmaf(rE, w.y, a.y + b.y));
                float h2 = siluf(fmaf(rE, w.z, a.z + b.z));
                float h3 = siluf(fmaf(rE, w.w, a.w + b.w));
                uint32_t hi0, lo0, hi1, lo1;
                split_pair(h0, h1, hi0, lo0);
                split_pair(h2, h3, hi1, lo1);
                uint32_t off = (uint32_t)((((q >> 1) ^ rx) << 4) + (q & 1) * 8);
                STS64(rowHi + off, hi0, hi1);
                STS64(rowLo + off, lo0, lo1);
            }
        }
    }
    __syncwarp();

    float* fout = out + (size_t)4 * E;
    float* outT = out + E;
    int Lmat = lane >> 3;

    #pragma unroll 1
    for (int mt = 0; mt < 2; mt++) {
        float D[8][4];
        uint32_t A3H[4][4], A3L[4][4];
        {
            uint32_t AH[4][4], AL[4][4];
            #pragma unroll
            for (int kt = 0; kt < 4; kt++) {
                int rr = m0 + mt * 16 + (Lmat & 1) * 8 + (lane & 7);
                int chunk = kt * 2 + (Lmat >> 1);
                uint32_t off = (uint32_t)(rr * 128 + ((chunk ^ (rr & 7)) << 4));
                ldmx4(AH[kt], aHi + off);
                ldmx4(AL[kt], aLo + off);
            }
            #pragma unroll
            for (int nt = 0; nt < 8; nt++) {
                float b0 = b2v[nt * 8 + tig * 2];
                float b1 = b2v[nt * 8 + tig * 2 + 1];
                D[nt][0] = b0; D[nt][1] = b1;
                D[nt][2] = b0; D[nt][3] = b1;
            }
            #pragma unroll
            for (int nt = 0; nt < 8; nt++) {
                #pragma unroll
                for (int kt = 0; kt < 4; kt++) {
                    uint4 w = __ldg(&g_WF2[(nt * 4 + kt) * 32 + lane]);
                    uint32_t bh[2] = { w.x, w.y };
                    uint32_t bl[2] = { w.z, w.w };
                    mma16816(D[nt], AH[kt], bh);
                    mma16816(D[nt], AH[kt], bl);
                    mma16816(D[nt], AL[kt], bh);
                }
            }
        }

        {
            int r0 = m0 + mt * 16 + gid;
            int r1 = r0 + 8;
            int e0 = base + r0, e1 = base + r1;
            #pragma unroll
            for (int nt = 0; nt < 8; nt++) {
                float v0 = siluf(D[nt][0]);
                float v1 = siluf(D[nt][1]);
                float v2 = siluf(D[nt][2]);
                float v3 = siluf(D[nt][3]);
                int col = nt * 8 + tig * 2;
                if (e0 < E)
                    *(float2*)(fout + (size_t)e0 * 64 + col) = make_float2(v0, v1);
                if (e1 < E)
                    *(float2*)(fout + (size_t)e1 * 64 + col) = make_float2(v2, v3);
                int kt = nt >> 1, hi = (nt & 1) * 2;
                split_pair(v0, v1, A3H[kt][hi],     A3L[kt][hi]);
                split_pair(v2, v3, A3H[kt][hi + 1], A3L[kt][hi + 1]);
            }
        }

        #pragma unroll
        for (int nt = 0; nt < 8; nt++) {
            float b0 = b3v[nt * 8 + tig * 2];
            float b1 = b3v[nt * 8 + tig * 2 + 1];
            D[nt][0] = b0; D[nt][1] = b1;
            D[nt][2] = b0; D[nt][3] = b1;
        }
        #pragma unroll
        for (int nt = 0; nt < 8; nt++) {
            #pragma unroll
            for (int kt = 0; kt < 4; kt++) {
                uint4 w = __ldg(&g_WF3[(nt * 4 + kt) * 32 + lane]);
                uint32_t bh[2] = { w.x, w.y };
                uint32_t bl[2] = { w.z, w.w };
                mma16816(D[nt], A3H[kt], bh);
                mma16816(D[nt], A3H[kt], bl);
                mma16816(D[nt], A3L[kt], bh);
            }
        }

        {
            float dv0 = 0.f, dv1 = 0.f;
            #pragma unroll
            for (int nt = 0; nt < 8; nt++) {
                int col = nt * 8 + tig * 2;
                float wa = w4v[col], wb = w4v[col + 1];
                dv0 = fmaf(siluf(D[nt][0]), wa, fmaf(siluf(D[nt][1]), wb, dv0));
                dv1 = fmaf(siluf(D[nt][2]), wa, fmaf(siluf(D[nt][3]), wb, dv1));
            }
            dv0 += __shfl_xor_sync(0xffffffffu, dv0, 1);
            dv0 += __shfl_xor_sync(0xffffffffu, dv0, 2);
            dv1 += __shfl_xor_sync(0xffffffffu, dv1, 1);
            dv1 += __shfl_xor_sync(0xffffffffu, dv1, 2);
            int rw = mt * 16 + (tig & 1) * 8 + gid;
            float dsel = (tig & 1) ? dv1 : dv0;
            float rr  = __shfl_sync(0xffffffffu, r,  rw);
            float cxx = __shfl_sync(0xffffffffu, cx, rw);
            float cyy = __shfl_sync(0xffffffffu, cy, rw);
            float czz = __shfl_sync(0xffffffffu, cz, rw);
            int ee = base + m0 + rw;
            float msc = __fdividef(tanhf(dsel), sqrtf(rr) + 1e-8f);
            if (tig < 2 && ee < E) {
                outT[3 * ee + 0] = cxx * msc;
                outT[3 * ee + 1] = cyy * msc;
                outT[3 * ee + 2] = czz * msc;
            }
        }
    }
}

extern "C" void kernel_launch(void* const* d_in, const int* in_sizes, int n_in,
                              void* d_out, int out_size) {
    const float* x  = (const float*)d_in[0];
    const float* hh = (const float*)d_in[1];
    const int* src  = (const int*)d_in[2];
    const int* dst  = (const int*)d_in[3];
    const float* W1 = (const float*)d_in[4];
    const float* b1 = (const float*)d_in[5];
    const float* W2 = (const float*)d_in[6];
    const float* b2 = (const float*)d_in[7];
    const float* W3 = (const float*)d_in[8];
    const float* b3 = (const float*)d_in[9];
    const float* W4 = (const float*)d_in[10];
    int N = in_sizes[0] / 3;
    int E = in_sizes[2];
    float* out = (float*)d_out;

    cudaFuncSetAttribute(edge_mma_kernel,
                         cudaFuncAttributeMaxDynamicSharedMemorySize, SMEM_TOTAL);
    cudaFuncSetAttribute(precompute_mma_kernel,
                         cudaFuncAttributeMaxDynamicSharedMemorySize, SMEM_TOTAL);

    pack_wf_kernel<<<8, 128>>>(W1, W2, W3);

    int pblocks = (N + 127) / 128;
    precompute_mma_kernel<<<pblocks, 128, SMEM_TOTAL>>>(x, hh, b1, N);

    int eblocks = (E + 127) / 128;
    edge_mma_kernel<<<eblocks, 128, SMEM_TOTAL>>>(src, dst, W1, b2, b3,
                                                  W4, out, E);
    (void)n_in; (void)out_size;
}

// round 8
// speedup vs baseline: 3.2886x; 1.3133x over previous
#include <cuda_runtime.h>
#include <cuda_bf16.h>
#include <cuda_fp16.h>
#include <math.h>
#include <stdint.h>

// ---------------------------------------------------------------------------
// EGNN edge message via warp-level HMMA.
//   Kernel 0: pack W1a/W1b (bf16 hi/lo) + W2/W3 (fp16 hi/lo) fragment tables
//   Kernel 1: P[n] = [ hh[n]@W1a + b1 | hh[n]@W1b ] via HMMA (bf16 x3)
//   Kernel 2 (per 128-edge block, 4 warps x 32 rows):
//     A tiles in SINGLE fp16; W in fp16 hi/lo (2 products) -> joint-mt:
//     each W fragment fetched once feeds both 16-row halves.
//     h1 = silu(Pa[s]+Pb[d]+r*W1row0); h2 = silu(h1@W2+b2) (features);
//     h3 = silu(h2@W3+b3); sc = tanh(h3.W4); trans = cd*sc/(sqrt(r)+eps)
// Output: [ radial (E) | trans (3E) | edge_feature (64E) ]
// ---------------------------------------------------------------------------

#define N_MAX_NODES 50048
__device__ float  g_P[(size_t)N_MAX_NODES * 128];
__device__ float4 g_Xp[N_MAX_NODES];
__device__ uint4  g_WF1A[1024];   // bf16 hi/lo (precompute)
__device__ uint4  g_WF1B[1024];   // bf16 hi/lo (precompute)
__device__ uint4  g_WF2[1024];    // fp16 hi/lo (edge)
__device__ uint4  g_WF3[1024];    // fp16 hi/lo (edge)

__device__ __forceinline__ float siluf(float v) {
    return __fdividef(v, 1.0f + __expf(-v));
}

__device__ __forceinline__ void split_pair_bf(float a, float b,
                                              uint32_t& hi, uint32_t& lo) {
    __nv_bfloat162 h2 = __floats2bfloat162_rn(a, b);
    float ra = a - __bfloat162float(h2.x);
    float rb = b - __bfloat162float(h2.y);
    __nv_bfloat162 l2 = __floats2bfloat162_rn(ra, rb);
    hi = *reinterpret_cast<uint32_t*>(&h2);
    lo = *reinterpret_cast<uint32_t*>(&l2);
}

__device__ __forceinline__ void split_pair_h(float a, float b,
                                             uint32_t& hi, uint32_t& lo) {
    __half2 h2 = __floats2half2_rn(a, b);
    float ra = a - __half2float(__low2half(h2));
    float rb = b - __half2float(__high2half(h2));
    __half2 l2 = __floats2half2_rn(ra, rb);
    hi = *reinterpret_cast<uint32_t*>(&h2);
    lo = *reinterpret_cast<uint32_t*>(&l2);
}

__device__ __forceinline__ uint32_t packh2(float a, float b) {
    __half2 h2 = __floats2half2_rn(a, b);
    return *reinterpret_cast<uint32_t*>(&h2);
}

// ---------------- Kernel 0: pack mma fragment tables -----------------------
__global__ void __launch_bounds__(128) pack_wf_kernel(
    const float* __restrict__ W1,
    const float* __restrict__ W2, const float* __restrict__ W3)
{
    int idx = blockIdx.x * 128 + threadIdx.x;
    if (idx >= 1024) return;
    int t = idx >> 5, l = idx & 31;
    int kt = t & 3, nt = t >> 2;
    int g = l >> 2, tg = l & 3;
    int k0 = kt * 16 + tg * 2;
    int n = nt * 8 + g;
    #pragma unroll
    for (int tab = 0; tab < 4; tab++) {
        const float* W;
        int roff = 0;
        uint4* dstv;
        if (tab == 0)      { W = W1; roff = 1;  dstv = g_WF1A; }
        else if (tab == 1) { W = W1; roff = 65; dstv = g_WF1B; }
        else if (tab == 2) { W = W2; dstv = g_WF2; }
        else               { W = W3; dstv = g_WF3; }
        float w00 = W[(roff + k0) * 64 + n],     w01 = W[(roff + k0 + 1) * 64 + n];
        float w10 = W[(roff + k0 + 8) * 64 + n], w11 = W[(roff + k0 + 9) * 64 + n];
        uint4 v;
        if (tab < 2) {
            split_pair_bf(w00, w01, v.x, v.z);
            split_pair_bf(w10, w11, v.y, v.w);
        } else {
            split_pair_h(w00, w01, v.x, v.z);
            split_pair_h(w10, w11, v.y, v.w);
        }
        dstv[idx] = v;
    }
}

// ------------------------------ mma helpers ---------------------------------
#define STS64(addr, v0, v1) \
    asm volatile("st.shared.v2.b32 [%0], {%1,%2};" \
                 :: "r"(addr), "r"(v0), "r"(v1) : "memory")

__device__ __forceinline__ void ldmx4(uint32_t* r, uint32_t addr) {
    asm volatile("ldmatrix.sync.aligned.m8n8.x4.shared.b16 {%0,%1,%2,%3}, [%4];"
        : "=r"(r[0]), "=r"(r[1]), "=r"(r[2]), "=r"(r[3]) : "r"(addr));
}

__device__ __forceinline__ void mma_bf(float* d, const uint32_t* a,
                                       const uint32_t* b) {
    asm volatile(
        "mma.sync.aligned.m16n8k16.row.col.f32.bf16.bf16.f32 "
        "{%0,%1,%2,%3}, {%4,%5,%6,%7}, {%8,%9}, {%0,%1,%2,%3};"
        : "+f"(d[0]), "+f"(d[1]), "+f"(d[2]), "+f"(d[3])
        : "r"(a[0]), "r"(a[1]), "r"(a[2]), "r"(a[3]), "r"(b[0]), "r"(b[1]));
}

__device__ __forceinline__ void mma_h(float* d, const uint32_t* a,
                                      const uint32_t* b) {
    asm volatile(
        "mma.sync.aligned.m16n8k16.row.col.f32.f16.f16.f32 "
        "{%0,%1,%2,%3}, {%4,%5,%6,%7}, {%8,%9}, {%0,%1,%2,%3};"
        : "+f"(d[0]), "+f"(d[1]), "+f"(d[2]), "+f"(d[3])
        : "r"(a[0]), "r"(a[1]), "r"(a[2]), "r"(a[3]), "r"(b[0]), "r"(b[1]));
}

// precompute smem layout (bf16 hi/lo, 128B rows x2)
#define PRE_AHI  0
#define PRE_ALO  16384
#define PRE_VEC  32768
#define SMEM_PRE 33792

// edge smem layout (fp16 single, 128B rows)
#define EDG_A    0
#define EDG_VEC  16384
#define SMEM_EDG 17408

// ---------------- Kernel 1: per-node projection via HMMA --------------------
__global__ void __launch_bounds__(128) precompute_mma_kernel(
    const float* __restrict__ x,
    const float* __restrict__ hh, const float* __restrict__ b1, int n_nodes)
{
    extern __shared__ char sm[];
    uint32_t smb = (uint32_t)__cvta_generic_to_shared(sm);
    int tid = threadIdx.x;
    int lane = tid & 31;
    int warp = tid >> 5;
    int m0 = warp * 32;
    int gid = lane >> 2, tig = lane & 3;

    float* b1v = (float*)(sm + PRE_VEC);
    if (tid < 64) b1v[tid] = b1[tid];

    int nb = blockIdx.x * 128;
    int node = nb + m0 + lane;
    if (node < n_nodes) {
        const float* xp = x + 3 * node;
        g_Xp[node] = make_float4(xp[0], xp[1], xp[2], 0.f);
    }

    uint32_t aHi = smb + PRE_AHI, aLo = smb + PRE_ALO;

    {
        int g = lane >> 3, c = lane & 7;
        #pragma unroll
        for (int j = 0; j < 8; j++) {
            int row = m0 + j * 4 + g;
            int n = nb + row;
            uint32_t rowHi = aHi + (uint32_t)row * 128;
            uint32_t rowLo = aLo + (uint32_t)row * 128;
            int rx = row & 7;
            #pragma unroll
            for (int half = 0; half < 2; half++) {
                int q = half * 8 + c;
                float4 a = (n < n_nodes)
                    ? *(const float4*)(hh + (size_t)n * 64 + q * 4)
                    : make_float4(0.f, 0.f, 0.f, 0.f);
                uint32_t hi0, lo0, hi1, lo1;
                split_pair_bf(a.x, a.y, hi0, lo0);
                split_pair_bf(a.z, a.w, hi1, lo1);
                uint32_t off = (uint32_t)((((q >> 1) ^ rx) << 4) + (q & 1) * 8);
                STS64(rowHi + off, hi0, hi1);
                STS64(rowLo + off, lo0, lo1);
            }
        }
    }
    __syncthreads();

    int Lmat = lane >> 3;
    #pragma unroll 1
    for (int mt = 0; mt < 2; mt++) {
        uint32_t AH[4][4], AL[4][4];
        #pragma unroll
        for (int kt = 0; kt < 4; kt++) {
            int rr = m0 + mt * 16 + (Lmat & 1) * 8 + (lane & 7);
            int chunk = kt * 2 + (Lmat >> 1);
            uint32_t off = (uint32_t)(rr * 128 + ((chunk ^ (rr & 7)) << 4));
            ldmx4(AH[kt], aHi + off);
            ldmx4(AL[kt], aLo + off);
        }
        int r0 = m0 + mt * 16 + gid;
        int r1 = r0 + 8;
        int n0 = nb + r0, n1 = nb + r1;

        #pragma unroll 1
        for (int half = 0; half < 2; half++) {
            const uint4* WF = half ? g_WF1B : g_WF1A;
            float D[8][4];
            #pragma unroll
            for (int nt = 0; nt < 8; nt++) {
                float b0 = half ? 0.f : b1v[nt * 8 + tig * 2];
                float b1x = half ? 0.f : b1v[nt * 8 + tig * 2 + 1];
                D[nt][0] = b0; D[nt][1] = b1x;
                D[nt][2] = b0; D[nt][3] = b1x;
            }
            #pragma unroll
            for (int nt = 0; nt < 8; nt++) {
                #pragma unroll
                for (int kt = 0; kt < 4; kt++) {
                    uint4 w = __ldg(&WF[(nt * 4 + kt) * 32 + lane]);
                    uint32_t bh[2] = { w.x, w.y };
                    uint32_t bl[2] = { w.z, w.w };
                    mma_bf(D[nt], AH[kt], bh);
                    mma_bf(D[nt], AH[kt], bl);
                    mma_bf(D[nt], AL[kt], bh);
                }
            }
            #pragma unroll
            for (int nt = 0; nt < 8; nt++) {
                int col = half * 64 + nt * 8 + tig * 2;
                if (n0 < n_nodes)
                    *(float2*)(g_P + (size_t)n0 * 128 + col) =
                        make_float2(D[nt][0], D[nt][1]);
                if (n1 < n_nodes)
                    *(float2*)(g_P + (size_t)n1 * 128 + col) =
                        make_float2(D[nt][2], D[nt][3]);
            }
        }
    }
}

// ---------------------------- Kernel 2: edges -------------------------------
__global__ void __launch_bounds__(128, 4) edge_mma_kernel(
    const int* __restrict__ src, const int* __restrict__ dst,
    const float* __restrict__ W1,
    const float* __restrict__ b2, const float* __restrict__ b3,
    const float* __restrict__ W4,
    float* __restrict__ out, int E)
{
    extern __shared__ char sm[];
    uint32_t smb = (uint32_t)__cvta_generic_to_shared(sm);
    int tid = threadIdx.x;
    int lane = tid & 31;
    int warp = tid >> 5;
    int m0 = warp * 32;
    int gid = lane >> 2, tig = lane & 3;

    float* w1r = (float*)(sm + EDG_VEC);
    float* b2v = (float*)(sm + EDG_VEC + 256);
    float* b3v = (float*)(sm + EDG_VEC + 512);
    float* w4v = (float*)(sm + EDG_VEC + 768);
    if (tid < 64) {
        w1r[tid] = W1[tid];
        b2v[tid] = b2[tid];
        b3v[tid] = b3[tid];
        w4v[tid] = W4[tid];
    }
    __syncthreads();

    int base = blockIdx.x * 128;
    int e = base + m0 + lane;
    bool valid = e < E;
    int s = 0, dn = 0;
    if (valid) { s = src[e]; dn = dst[e]; }
    float4 xs = g_Xp[s], xd = g_Xp[dn];
    float cx = xs.x - xd.x, cy = xs.y - xd.y, cz = xs.z - xd.z;
    float r = cx * cx + cy * cy + cz * cz;
    if (valid) out[e] = r;

    uint32_t aT = smb + EDG_A;

    // ---- layer 1: cooperative coalesced gather + silu -> fp16 A tile ----
    {
        const float4* w1q = (const float4*)w1r;
        int g = lane >> 3, c = lane & 7;
        const char* Pb = (const char*)g_P;
        #pragma unroll
        for (int j = 0; j < 8; j++) {
            int sl = j * 4 + g;
            int sE = __shfl_sync(0xffffffffu, s,  sl);
            int dE = __shfl_sync(0xffffffffu, dn, sl);
            float rE = __shfl_sync(0xffffffffu, r, sl);
            int row = m0 + j * 4 + g;
            uint32_t rowB = aT + (uint32_t)row * 128;
            int rx = row & 7;
            #pragma unroll
            for (int half = 0; half < 2; half++) {
                int q = half * 8 + c;
                float4 a = *(const float4*)(Pb + (size_t)sE * 512 + half * 128 + c * 16);
                float4 b = *(const float4*)(Pb + (size_t)dE * 512 + 256 + half * 128 + c * 16);
                float4 w = w1q[q];
                float h0 = siluf(fmaf(rE, w.x, a.x + b.x));
                float h1 = siluf(fmaf(rE, w.y, a.y + b.y));
                float h2 = siluf(fmaf(rE, w.z, a.z + b.z));
                float h3 = siluf(fmaf(rE, w.w, a.w + b.w));
                // cols 4q..4q+3 -> bytes 8q..8q+7 of the 128B row
                int chunk = q >> 1;
                uint32_t off = (uint32_t)(((chunk ^ rx) << 4) + (q & 1) * 8);
                STS64(rowB + off, packh2(h0, h1), packh2(h2, h3));
            }
        }
    }
    __syncwarp();

    float* fout = out + (size_t)4 * E;
    float* outT = out + E;
    int Lmat = lane >> 3;

    // ---- A fragments for both 16-row halves (fp16 single) ----
    uint32_t AH[2][4][4];
    #pragma unroll
    for (int mt = 0; mt < 2; mt++) {
        #pragma unroll
        for (int kt = 0; kt < 4; kt++) {
            int rr = m0 + mt * 16 + (Lmat & 1) * 8 + (lane & 7);
            int chunk = kt * 2 + (Lmat >> 1);
            uint32_t off = (uint32_t)(rr * 128 + ((chunk ^ (rr & 7)) << 4));
            ldmx4(AH[mt][kt], aT + off);
        }
    }

    // ---- layer 2: joint-mt, nt processed in pairs, W fetched once ----
    uint32_t A3H[2][4][4];
    #pragma unroll
    for (int ntp = 0; ntp < 4; ntp++) {
        float D[2][2][4];
        #pragma unroll
        for (int nn = 0; nn < 2; nn++) {
            int nt = 2 * ntp + nn;
            float b0 = b2v[nt * 8 + tig * 2];
            float b1 = b2v[nt * 8 + tig * 2 + 1];
            #pragma unroll
            for (int mt = 0; mt < 2; mt++) {
                D[mt][nn][0] = b0; D[mt][nn][1] = b1;
                D[mt][nn][2] = b0; D[mt][nn][3] = b1;
            }
        }
        #pragma unroll
        for (int nn = 0; nn < 2; nn++) {
            int nt = 2 * ntp + nn;
            #pragma unroll
            for (int kt = 0; kt < 4; kt++) {
                uint4 w = __ldg(&g_WF2[(nt * 4 + kt) * 32 + lane]);
                uint32_t bh[2] = { w.x, w.y };
                uint32_t bl[2] = { w.z, w.w };
                mma_h(D[0][nn], AH[0][kt], bh);
                mma_h(D[0][nn], AH[0][kt], bl);
                mma_h(D[1][nn], AH[1][kt], bh);
                mma_h(D[1][nn], AH[1][kt], bl);
            }
        }
        // epilogue for this nt pair: features + A3 fragments
        #pragma unroll
        for (int mt = 0; mt < 2; mt++) {
            int r0 = m0 + mt * 16 + gid;
            int r1 = r0 + 8;
            int e0 = base + r0, e1 = base + r1;
            #pragma unroll
            for (int nn = 0; nn < 2; nn++) {
                int nt = 2 * ntp + nn;
                float v0 = siluf(D[mt][nn][0]);
                float v1 = siluf(D[mt][nn][1]);
                float v2 = siluf(D[mt][nn][2]);
                float v3 = siluf(D[mt][nn][3]);
                int col = nt * 8 + tig * 2;
                if (e0 < E)
                    *(float2*)(fout + (size_t)e0 * 64 + col) = make_float2(v0, v1);
                if (e1 < E)
                    *(float2*)(fout + (size_t)e1 * 64 + col) = make_float2(v2, v3);
                A3H[mt][ntp][nn * 2 + 0] = packh2(v0, v1);
                A3H[mt][ntp][nn * 2 + 1] = packh2(v2, v3);
            }
        }
    }

    // ---- layer 3: joint-mt, dv accumulated per nt pair ----
    float dv[2][2] = { {0.f, 0.f}, {0.f, 0.f} };
    #pragma unroll
    for (int ntp = 0; ntp < 4; ntp++) {
        float D[2][2][4];
        #pragma unroll
        for (int nn = 0; nn < 2; nn++) {
            int nt = 2 * ntp + nn;
            float b0 = b3v[nt * 8 + tig * 2];
            float b1 = b3v[nt * 8 + tig * 2 + 1];
            #pragma unroll
            for (int mt = 0; mt < 2; mt++) {
                D[mt][nn][0] = b0; D[mt][nn][1] = b1;
                D[mt][nn][2] = b0; D[mt][nn][3] = b1;
            }
        }
        #pragma unroll
        for (int nn = 0; nn < 2; nn++) {
            int nt = 2 * ntp + nn;
            #pragma unroll
            for (int kt = 0; kt < 4; kt++) {
                uint4 w = __ldg(&g_WF3[(nt * 4 + kt) * 32 + lane]);
                uint32_t bh[2] = { w.x, w.y };
                uint32_t bl[2] = { w.z, w.w };
                mma_h(D[0][nn], A3H[0][kt], bh);
                mma_h(D[0][nn], A3H[0][kt], bl);
                mma_h(D[1][nn], A3H[1][kt], bh);
                mma_h(D[1][nn], A3H[1][kt], bl);
            }
        }
        #pragma unroll
        for (int mt = 0; mt < 2; mt++) {
            #pragma unroll
            for (int nn = 0; nn < 2; nn++) {
                int nt = 2 * ntp + nn;
                int col = nt * 8 + tig * 2;
                float wa = w4v[col], wb = w4v[col + 1];
                dv[mt][0] = fmaf(siluf(D[mt][nn][0]), wa,
                            fmaf(siluf(D[mt][nn][1]), wb, dv[mt][0]));
                dv[mt][1] = fmaf(siluf(D[mt][nn][2]), wa,
                            fmaf(siluf(D[mt][nn][3]), wb, dv[mt][1]));
            }
        }
    }

    // ---- trans output ----
    #pragma unroll
    for (int mt = 0; mt < 2; mt++) {
        float d0 = dv[mt][0], d1 = dv[mt][1];
        d0 += __shfl_xor_sync(0xffffffffu, d0, 1);
        d0 += __shfl_xor_sync(0xffffffffu, d0, 2);
        d1 += __shfl_xor_sync(0xffffffffu, d1, 1);
        d1 += __shfl_xor_sync(0xffffffffu, d1, 2);
        int rw = mt * 16 + (tig & 1) * 8 + gid;
        float dsel = (tig & 1) ? d1 : d0;
        float rr  = __shfl_sync(0xffffffffu, r,  rw);
        float cxx = __shfl_sync(0xffffffffu, cx, rw);
        float cyy = __shfl_sync(0xffffffffu, cy, rw);
        float czz = __shfl_sync(0xffffffffu, cz, rw);
        int ee = base + m0 + rw;
        float msc = __fdividef(tanhf(dsel), sqrtf(rr) + 1e-8f);
        if (tig < 2 && ee < E) {
            outT[3 * ee + 0] = cxx * msc;
            outT[3 * ee + 1] = cyy * msc;
            outT[3 * ee + 2] = czz * msc;
        }
    }
}

extern "C" void kernel_launch(void* const* d_in, const int* in_sizes, int n_in,
                              void* d_out, int out_size) {
    const float* x  = (const float*)d_in[0];
    const float* hh = (const float*)d_in[1];
    const int* src  = (const int*)d_in[2];
    const int* dst  = (const int*)d_in[3];
    const float* W1 = (const float*)d_in[4];
    const float* b1 = (const float*)d_in[5];
    const float* W2 = (const float*)d_in[6];
    const float* b2 = (const float*)d_in[7];
    const float* W3 = (const float*)d_in[8];
    const float* b3 = (const float*)d_in[9];
    const float* W4 = (const float*)d_in[10];
    int N = in_sizes[0] / 3;
    int E = in_sizes[2];
    float* out = (float*)d_out;

    cudaFuncSetAttribute(precompute_mma_kernel,
                         cudaFuncAttributeMaxDynamicSharedMemorySize, SMEM_PRE);
    cudaFuncSetAttribute(edge_mma_kernel,
                         cudaFuncAttributeMaxDynamicSharedMemorySize, SMEM_EDG);

    pack_wf_kernel<<<8, 128>>>(W1, W2, W3);

    int pblocks = (N + 127) / 128;
    precompute_mma_kernel<<<pblocks, 128, SMEM_PRE>>>(x, hh, b1, N);

    int eblocks = (E + 127) / 128;
    edge_mma_kernel<<<eblocks, 128, SMEM_EDG>>>(src, dst, W1, b2, b3,
                                                W4, out, E);
    (void)n_in; (void)out_size;
}